// round 1
// baseline (speedup 1.0000x reference)
#include <cuda_runtime.h>
#include <math.h>

#define NT 8192
#define CD 1024
#define HD 4096

// ---------------- scratch (static device globals; no runtime allocation) ----
__device__ __align__(16) float g_xln[NT * CD];
__device__ __align__(16) float g_r[NT * CD];
__device__ __align__(16) float g_g[NT * CD];
__device__ __align__(16) float g_s[NT * CD];
__device__ __align__(16) float g_h[NT * CD];
__device__ __align__(16) float g_a[NT * CD];
__device__ __align__(16) float g_hr[NT * HD];
__device__ float g_scale[NT];
__device__ int g_cnt[3];
__device__ int g_list[3 * NT];

// ---------------- helpers ---------------------------------------------------
__device__ __forceinline__ unsigned long long ffma2(unsigned long long a,
                                                    unsigned long long b,
                                                    unsigned long long c) {
    unsigned long long d;
    asm("fma.rn.f32x2 %0, %1, %2, %3;" : "=l"(d) : "l"(a), "l"(b), "l"(c));
    return d;
}
__device__ __forceinline__ float2 unpack2(unsigned long long v) {
    float2 r;
    asm("mov.b64 {%0, %1}, %2;" : "=f"(r.x), "=f"(r.y) : "l"(v));
    return r;
}
__device__ __forceinline__ float sigf(float x) { return 1.0f / (1.0f + expf(-x)); }

union F4 { float4 f; unsigned long long u[2]; };

enum { EPI_STORE = 0, EPI_ADDX = 1, EPI_SIGMUL = 2, EPI_RELUSQ = 3, EPI_GATE = 4, EPI_SCATTER = 5 };

template <int EPI>
__device__ __forceinline__ void emit_row(int row, int col, const float v[8], int M,
                                         const float* __restrict__ aux,
                                         const int* __restrict__ sidx,
                                         const float* __restrict__ scl,
                                         float* __restrict__ C, int ldc) {
    if (row >= M) return;
    if (EPI == EPI_SCATTER) {
        int orow = sidx[row];
        float sc = scl[orow];
        float* p = C + (size_t)orow * ldc + col;
#pragma unroll
        for (int q = 0; q < 8; q += 4) {
            float4 c = *(float4*)(p + q);
            c.x += v[q + 0] * sc; c.y += v[q + 1] * sc;
            c.z += v[q + 2] * sc; c.w += v[q + 3] * sc;
            *(float4*)(p + q) = c;
        }
        return;
    }
    float* p = C + (size_t)row * ldc + col;
    const float* ap = (EPI == EPI_ADDX || EPI == EPI_SIGMUL || EPI == EPI_GATE)
                          ? aux + (size_t)row * ldc + col : nullptr;
#pragma unroll
    for (int q = 0; q < 8; q += 4) {
        float t0 = v[q + 0], t1 = v[q + 1], t2 = v[q + 2], t3 = v[q + 3];
        if (EPI == EPI_ADDX) {
            float4 a = *(const float4*)(ap + q);
            t0 += a.x; t1 += a.y; t2 += a.z; t3 += a.w;
        }
        if (EPI == EPI_SIGMUL) {
            float4 a = *(const float4*)(ap + q);
            t0 = sigf(a.x) * t0; t1 = sigf(a.y) * t1;
            t2 = sigf(a.z) * t2; t3 = sigf(a.w) * t3;
        }
        if (EPI == EPI_RELUSQ) {
            t0 = fmaxf(t0, 0.f); t0 *= t0;
            t1 = fmaxf(t1, 0.f); t1 *= t1;
            t2 = fmaxf(t2, 0.f); t2 *= t2;
            t3 = fmaxf(t3, 0.f); t3 *= t3;
        }
        if (EPI == EPI_GATE) {
            float4 a = *(const float4*)(ap + q);
            t0 = a.x * sigf(t0); t1 = a.y * sigf(t1);
            t2 = a.z * sigf(t2); t3 = a.w * sigf(t3);
        }
        *(float4*)(p + q) = make_float4(t0, t1, t2, t3);
    }
}

// ------------- 128x128x8 fp32 GEMM with packed f32x2 FMA ---------------------
// C[M,N] (+epilogue) = A[M,K] @ B[K,N].  A rows optionally gathered via gidx.
// M can be dynamic (read from Mptr) for expert dispatch; surplus blocks exit.
template <int EPI>
__global__ void __launch_bounds__(256, 2)
gemm_k(const float* __restrict__ A, const float* __restrict__ B,
       int Mstat, const int* __restrict__ Mptr, int K, int ldb,
       const int* __restrict__ gidx,
       const float* __restrict__ aux,
       const int* __restrict__ sidx, const float* __restrict__ scl,
       float* __restrict__ Cout, int ldc) {
    int M = Mptr ? *Mptr : Mstat;
    int bm = blockIdx.x * 128;
    if (bm >= M) return;
    int bn = blockIdx.y * 128;

    __shared__ __align__(16) float As[8][132];
    __shared__ __align__(16) float Bs[8][264];   // duplicated (b,b) pairs

    int tid = threadIdx.x;
    int arow = tid >> 1, ac4 = (tid & 1) * 4;
    int brow = tid >> 5, bc4 = tid & 31;

    int rl = bm + arow;
    int rA = (rl < M) ? rl : (M - 1);
    if (gidx) rA = gidx[rA];
    const float* aptr = A + (size_t)rA * K + ac4;
    const float* bptr = B + (size_t)brow * ldb + bn + bc4 * 4;

    unsigned long long acc[4][8];
#pragma unroll
    for (int i = 0; i < 4; i++)
#pragma unroll
        for (int j = 0; j < 8; j++) acc[i][j] = 0ull;

    int tx = tid & 15, ty = tid >> 4;

    for (int kt = 0; kt < K; kt += 8) {
        float4 av = *(const float4*)(aptr + kt);
        float4 bv = *(const float4*)(bptr + (size_t)kt * ldb);
        As[ac4 + 0][arow] = av.x; As[ac4 + 1][arow] = av.y;
        As[ac4 + 2][arow] = av.z; As[ac4 + 3][arow] = av.w;
        *(float4*)&Bs[brow][bc4 * 8]     = make_float4(bv.x, bv.x, bv.y, bv.y);
        *(float4*)&Bs[brow][bc4 * 8 + 4] = make_float4(bv.z, bv.z, bv.w, bv.w);
        __syncthreads();
#pragma unroll
        for (int k = 0; k < 8; k++) {
            F4 a0, a1, b0, b1, b2, b3;
            a0.f = *(const float4*)&As[k][ty * 8];
            a1.f = *(const float4*)&As[k][ty * 8 + 4];
            b0.f = *(const float4*)&Bs[k][tx * 16];
            b1.f = *(const float4*)&Bs[k][tx * 16 + 4];
            b2.f = *(const float4*)&Bs[k][tx * 16 + 8];
            b3.f = *(const float4*)&Bs[k][tx * 16 + 12];
            unsigned long long ap[4] = {a0.u[0], a0.u[1], a1.u[0], a1.u[1]};
            unsigned long long bd[8] = {b0.u[0], b0.u[1], b1.u[0], b1.u[1],
                                        b2.u[0], b2.u[1], b3.u[0], b3.u[1]};
#pragma unroll
            for (int i = 0; i < 4; i++)
#pragma unroll
                for (int j = 0; j < 8; j++)
                    acc[i][j] = ffma2(ap[i], bd[j], acc[i][j]);
        }
        __syncthreads();
    }

    int ncol = bn + tx * 8;
#pragma unroll
    for (int i = 0; i < 4; i++) {
        float lo[8], hi[8];
#pragma unroll
        for (int j = 0; j < 8; j++) {
            float2 p = unpack2(acc[i][j]);
            lo[j] = p.x; hi[j] = p.y;
        }
        emit_row<EPI>(bm + ty * 8 + 2 * i,     ncol, lo, M, aux, sidx, scl, Cout, ldc);
        emit_row<EPI>(bm + ty * 8 + 2 * i + 1, ncol, hi, M, aux, sidx, scl, Cout, ldc);
    }
}

// ---------------- block reduce ----------------------------------------------
__device__ __forceinline__ float blockReduceSum(float v) {
    __shared__ float sh[8];
#pragma unroll
    for (int o = 16; o > 0; o >>= 1) v += __shfl_down_sync(0xffffffffu, v, o);
    int w = threadIdx.x >> 5, l = threadIdx.x & 31;
    if (l == 0) sh[w] = v;
    __syncthreads();
    if (threadIdx.x < 8) {
        float r = sh[threadIdx.x];
#pragma unroll
        for (int o = 4; o > 0; o >>= 1) r += __shfl_down_sync(0x000000ffu, r, o);
        if (threadIdx.x == 0) sh[0] = r;
    }
    __syncthreads();
    float res = sh[0];
    __syncthreads();
    return res;
}

// ---------------- LN1 -------------------------------------------------------
__global__ void ln_kernel(const float* __restrict__ x, const float* __restrict__ w,
                          const float* __restrict__ b, float* __restrict__ out) {
    int row = blockIdx.x;
    int tid = threadIdx.x;
    float4 v = ((const float4*)(x + (size_t)row * CD))[tid];
    float s = v.x + v.y + v.z + v.w;
    s = blockReduceSum(s);
    float mean = s * (1.0f / CD);
    float dx = v.x - mean, dy = v.y - mean, dz = v.z - mean, dw = v.w - mean;
    float s2 = dx * dx + dy * dy + dz * dz + dw * dw;
    s2 = blockReduceSum(s2);
    float rstd = 1.0f / sqrtf(s2 * (1.0f / CD) + 1e-5f);
    float4 wv = ((const float4*)w)[tid];
    float4 bv = ((const float4*)b)[tid];
    float4 o = make_float4(dx * rstd * wv.x + bv.x, dy * rstd * wv.y + bv.y,
                           dz * rstd * wv.z + bv.z, dw * rstd * wv.w + bv.w);
    ((float4*)(out + (size_t)row * CD))[tid] = o;
}

// ---------------- LN2 + routing (conf/diff/affinity/bids/argmax/lists) -------
__global__ void ln2_route_kernel(const float* __restrict__ x2, const float* __restrict__ w,
                                 const float* __restrict__ b,
                                 const float* __restrict__ conf_rwkv,
                                 const float* __restrict__ conf_trans,
                                 const float* __restrict__ w_diff,
                                 const float* __restrict__ W_aff,
                                 const float* __restrict__ capital,
                                 float* __restrict__ h_out, float* __restrict__ scale_out,
                                 int* __restrict__ cnt, int* __restrict__ lst) {
    int row = blockIdx.x;
    int tid = threadIdx.x;
    float4 v = ((const float4*)(x2 + (size_t)row * CD))[tid];
    float s = v.x + v.y + v.z + v.w;
    s = blockReduceSum(s);
    float mean = s * (1.0f / CD);
    float dx = v.x - mean, dy = v.y - mean, dz = v.z - mean, dw = v.w - mean;
    float s2 = dx * dx + dy * dy + dz * dz + dw * dw;
    s2 = blockReduceSum(s2);
    float rstd = 1.0f / sqrtf(s2 * (1.0f / CD) + 1e-5f);
    float4 wv = ((const float4*)w)[tid];
    float4 bv = ((const float4*)b)[tid];
    float4 o = make_float4(dx * rstd * wv.x + bv.x, dy * rstd * wv.y + bv.y,
                           dz * rstd * wv.z + bv.z, dw * rstd * wv.w + bv.w);
    ((float4*)(h_out + (size_t)row * CD))[tid] = o;

    float p[7];
    float4 c0 = ((const float4*)conf_rwkv)[tid];
    float4 c1 = ((const float4*)(conf_rwkv + CD))[tid];
    float4 ct = ((const float4*)conf_trans)[tid];
    float4 wd = ((const float4*)w_diff)[tid];
    p[0] = o.x * c0.x + o.y * c0.y + o.z * c0.z + o.w * c0.w;
    p[1] = o.x * c1.x + o.y * c1.y + o.z * c1.z + o.w * c1.w;
    p[2] = o.x * ct.x + o.y * ct.y + o.z * ct.z + o.w * ct.w;
    p[3] = o.x * wd.x + o.y * wd.y + o.z * wd.z + o.w * wd.w;
    const float* wa = W_aff + (size_t)tid * 4 * 3;   // (C,3) row-major
#pragma unroll
    for (int e = 0; e < 3; e++)
        p[4 + e] = o.x * wa[0 + e] + o.y * wa[3 + e] + o.z * wa[6 + e] + o.w * wa[9 + e];

    __shared__ float red[7][8];
    int wid = tid >> 5, lid = tid & 31;
#pragma unroll
    for (int q = 0; q < 7; q++) {
        float vv = p[q];
#pragma unroll
        for (int o2 = 16; o2 > 0; o2 >>= 1) vv += __shfl_down_sync(0xffffffffu, vv, o2);
        if (lid == 0) red[q][wid] = vv;
    }
    __syncthreads();
    if (tid == 0) {
        float d[7];
#pragma unroll
        for (int q = 0; q < 7; q++) {
            float t = 0.f;
#pragma unroll
            for (int k = 0; k < 8; k++) t += red[q][k];
            d[q] = t;
        }
        float cf[3] = {sigf(d[0]), sigf(d[1]), sigf(d[2])};
        float diff = sigf(d[3]);
        float bids[3];
#pragma unroll
        for (int e = 0; e < 3; e++) bids[e] = cf[e] * capital[e] * diff + d[4 + e];
        int wdx = 0;
        float best = bids[0];
        if (bids[1] > best) { best = bids[1]; wdx = 1; }
        if (bids[2] > best) { best = bids[2]; wdx = 2; }
        float wc = cf[wdx];
        scale_out[row] = wc / (wc + 1e-6f);
        int pos = atomicAdd(&cnt[wdx], 1);
        lst[wdx * NT + pos] = row;
    }
}

__global__ void zero_cnt_kernel(int* c) {
    if (threadIdx.x < 3) c[threadIdx.x] = 0;
}

// ---------------- launch ------------------------------------------------------
extern "C" void kernel_launch(void* const* d_in, const int* in_sizes, int n_in,
                              void* d_out, int out_size) {
    const float* x       = (const float*)d_in[0];
    const float* capital = (const float*)d_in[2];
    const float* ln1w = (const float*)d_in[3], *ln1b = (const float*)d_in[4];
    const float* ln2w = (const float*)d_in[5], *ln2b = (const float*)d_in[6];
    const float* Wr = (const float*)d_in[7], *Wv = (const float*)d_in[8];
    const float* Wo = (const float*)d_in[9], *Ws = (const float*)d_in[10];
    const float* Kr = (const float*)d_in[11], *Vr = (const float*)d_in[12];
    const float* confr = (const float*)d_in[13];
    const float* W1 = (const float*)d_in[14], *W2 = (const float*)d_in[15];
    const float* W3 = (const float*)d_in[16];
    const float* conft = (const float*)d_in[17], *wdiff = (const float*)d_in[18];
    const float* Waff = (const float*)d_in[19];
    float* out = (float*)d_out;

    void* p;
    cudaGetSymbolAddress(&p, g_xln);   float* xln   = (float*)p;
    cudaGetSymbolAddress(&p, g_r);     float* rb    = (float*)p;
    cudaGetSymbolAddress(&p, g_g);     float* gb    = (float*)p;
    cudaGetSymbolAddress(&p, g_s);     float* sb    = (float*)p;
    cudaGetSymbolAddress(&p, g_h);     float* hb    = (float*)p;
    cudaGetSymbolAddress(&p, g_a);     float* ab    = (float*)p;
    cudaGetSymbolAddress(&p, g_hr);    float* hrb   = (float*)p;
    cudaGetSymbolAddress(&p, g_scale); float* sclp  = (float*)p;
    cudaGetSymbolAddress(&p, g_cnt);   int*   cnt   = (int*)p;
    cudaGetSymbolAddress(&p, g_list);  int*   lst   = (int*)p;

    dim3 blk(256);
    dim3 gC(NT / 128, CD / 128);   // (64, 8)
    dim3 gH(NT / 128, HD / 128);   // (64, 32)

    zero_cnt_kernel<<<1, 32>>>(cnt);
    ln_kernel<<<NT, 256>>>(x, ln1w, ln1b, xln);

    // attention path (fp32-exact: feeds routing)
    gemm_k<EPI_STORE><<<gC, blk>>>(xln, Wr, NT, nullptr, CD, CD, nullptr, nullptr, nullptr, nullptr, rb, CD);
    gemm_k<EPI_SIGMUL><<<gC, blk>>>(xln, Wv, NT, nullptr, CD, CD, nullptr, rb, nullptr, nullptr, gb, CD);
    gemm_k<EPI_STORE><<<gC, blk>>>(xln, Ws, NT, nullptr, CD, CD, nullptr, nullptr, nullptr, nullptr, sb, CD);
    gemm_k<EPI_ADDX><<<gC, blk>>>(gb, Wo, NT, nullptr, CD, CD, nullptr, x, nullptr, nullptr, out, CD);

    // LN2 + routing: h, scale, per-expert token lists
    ln2_route_kernel<<<NT, 256>>>(out, ln2w, ln2b, confr, conft, wdiff, Waff,
                                  capital, hb, sclp, cnt, lst);

    // transformer expert (winner == 2), sparse
    gemm_k<EPI_STORE><<<gC, blk>>>(hb, W1, 0, cnt + 2, CD, CD, lst + 2 * NT, nullptr, nullptr, nullptr, ab, CD);
    gemm_k<EPI_GATE><<<gC, blk>>>(sb, W2, 0, cnt + 2, CD, CD, lst + 2 * NT, ab, nullptr, nullptr, ab, CD);
    gemm_k<EPI_SCATTER><<<gC, blk>>>(ab, W3, 0, cnt + 2, CD, CD, nullptr, nullptr, lst + 2 * NT, sclp, out, CD);

    // RWKV experts (winner == e), sparse
    for (int e = 0; e < 2; e++) {
        gemm_k<EPI_RELUSQ><<<gH, blk>>>(hb, Kr + (size_t)e * CD * HD, 0, cnt + e, CD, HD,
                                        lst + e * NT, nullptr, nullptr, nullptr, hrb, HD);
        gemm_k<EPI_SCATTER><<<gC, blk>>>(hrb, Vr + (size_t)e * HD * CD, 0, cnt + e, HD, CD,
                                         nullptr, nullptr, lst + e * NT, sclp, out, CD);
    }
}

// round 2
// speedup vs baseline: 2.8871x; 2.8871x over previous
#include <cuda_runtime.h>
#include <math.h>

#define NT 8192
#define CD 1024
#define HD 4096

// ---------------- scratch (static device globals; no runtime allocation) ----
__device__ __align__(16) float g_xln[NT * CD];
__device__ __align__(16) float g_r[NT * CD];
__device__ __align__(16) float g_g[NT * CD];
__device__ __align__(16) float g_s[NT * CD];
__device__ __align__(16) float g_h[NT * CD];
__device__ __align__(16) float g_a[NT * CD];
__device__ __align__(16) float g_hr[NT * HD];
__device__ float g_scale[NT];
__device__ int g_cnt[3];
__device__ int g_list[3 * NT];

// ---------------- helpers ---------------------------------------------------
__device__ __forceinline__ unsigned long long ffma2(unsigned long long a,
                                                    unsigned long long b,
                                                    unsigned long long c) {
    unsigned long long d;
    asm("fma.rn.f32x2 %0, %1, %2, %3;" : "=l"(d) : "l"(a), "l"(b), "l"(c));
    return d;
}
__device__ __forceinline__ unsigned long long dup2(float v) {
    unsigned long long d;
    unsigned int u = __float_as_uint(v);
    asm("mov.b64 %0, {%1, %2};" : "=l"(d) : "r"(u), "r"(u));
    return d;
}
__device__ __forceinline__ float2 unpack2(unsigned long long v) {
    float2 r;
    asm("mov.b64 {%0, %1}, %2;" : "=f"(r.x), "=f"(r.y) : "l"(v));
    return r;
}
__device__ __forceinline__ float sigf(float x) { return 1.0f / (1.0f + expf(-x)); }

union F4 { float4 f; unsigned long long u[2]; };

enum { EPI_STORE = 0, EPI_ADDX = 1, EPI_SIGMUL = 2, EPI_RELUSQ = 3, EPI_GATE = 4, EPI_SCATTER = 5 };

template <int EPI>
__device__ __forceinline__ void emit_row(int row, int col, const float v[8], int M,
                                         const float* __restrict__ aux,
                                         const int* __restrict__ sidx,
                                         const float* __restrict__ scl,
                                         float* __restrict__ C, int ldc) {
    if (row >= M) return;
    if (EPI == EPI_SCATTER) {
        int orow = sidx[row];
        float sc = scl[orow];
        float* p = C + (size_t)orow * ldc + col;
#pragma unroll
        for (int q = 0; q < 8; q += 4) {
            float4 c = *(float4*)(p + q);
            c.x += v[q + 0] * sc; c.y += v[q + 1] * sc;
            c.z += v[q + 2] * sc; c.w += v[q + 3] * sc;
            *(float4*)(p + q) = c;
        }
        return;
    }
    float* p = C + (size_t)row * ldc + col;
    const float* ap = (EPI == EPI_ADDX || EPI == EPI_SIGMUL || EPI == EPI_GATE)
                          ? aux + (size_t)row * ldc + col : nullptr;
#pragma unroll
    for (int q = 0; q < 8; q += 4) {
        float t0 = v[q + 0], t1 = v[q + 1], t2 = v[q + 2], t3 = v[q + 3];
        if (EPI == EPI_ADDX) {
            float4 a = *(const float4*)(ap + q);
            t0 += a.x; t1 += a.y; t2 += a.z; t3 += a.w;
        }
        if (EPI == EPI_SIGMUL) {
            float4 a = *(const float4*)(ap + q);
            t0 = sigf(a.x) * t0; t1 = sigf(a.y) * t1;
            t2 = sigf(a.z) * t2; t3 = sigf(a.w) * t3;
        }
        if (EPI == EPI_RELUSQ) {
            t0 = fmaxf(t0, 0.f); t0 *= t0;
            t1 = fmaxf(t1, 0.f); t1 *= t1;
            t2 = fmaxf(t2, 0.f); t2 *= t2;
            t3 = fmaxf(t3, 0.f); t3 *= t3;
        }
        if (EPI == EPI_GATE) {
            float4 a = *(const float4*)(ap + q);
            t0 = a.x * sigf(t0); t1 = a.y * sigf(t1);
            t2 = a.z * sigf(t2); t3 = a.w * sigf(t3);
        }
        *(float4*)(p + q) = make_float4(t0, t1, t2, t3);
    }
}

// ------------- 128x128 fp32 GEMM, BK=16, double-buffered, dedup-B f32x2 ------
// C[M,N] (+epilogue) = A[M,K] @ B[K,N].  A rows optionally gathered via gidx.
// M can be dynamic (read from Mptr) for expert dispatch; surplus blocks exit.
template <int EPI>
__global__ void __launch_bounds__(256, 2)
gemm_k(const float* __restrict__ A, const float* __restrict__ B,
       int Mstat, const int* __restrict__ Mptr, int K, int ldb,
       const int* __restrict__ gidx,
       const float* __restrict__ aux,
       const int* __restrict__ sidx, const float* __restrict__ scl,
       float* __restrict__ Cout, int ldc) {
    int M = Mptr ? *Mptr : Mstat;
    int bm = blockIdx.x * 128;
    if (bm >= M) return;
    int bn = blockIdx.y * 128;

    __shared__ __align__(16) float As[2][16][132];  // k-major (transposed A)
    __shared__ __align__(16) float Bs[2][16][128];

    int tid = threadIdx.x;
    // global->smem mappings
    int arow = tid >> 1;            // 0..127
    int ak8  = (tid & 1) * 8;       // 0 / 8
    int brow = tid >> 4;            // 0..15
    int bcol = (tid & 15) * 8;      // 0..120

    int rl = bm + arow;
    int rA = (rl < M) ? rl : (M - 1);
    if (gidx) rA = gidx[rA];
    const float* aptr = A + (size_t)rA * K + ak8;
    const float* bptr = B + (size_t)brow * ldb + bn + bcol;

    int tx = tid & 15, ty = tid >> 4;
    int ty8 = ty * 8, tx8 = tx * 8;

    unsigned long long acc[4][8];
#pragma unroll
    for (int i = 0; i < 4; i++)
#pragma unroll
        for (int j = 0; j < 8; j++) acc[i][j] = 0ull;

    // prologue: load tile 0 into regs, stage to smem buf 0
    float4 pa0 = *(const float4*)(aptr);
    float4 pa1 = *(const float4*)(aptr + 4);
    float4 pb0 = *(const float4*)(bptr);
    float4 pb1 = *(const float4*)(bptr + 4);
    As[0][ak8 + 0][arow] = pa0.x; As[0][ak8 + 1][arow] = pa0.y;
    As[0][ak8 + 2][arow] = pa0.z; As[0][ak8 + 3][arow] = pa0.w;
    As[0][ak8 + 4][arow] = pa1.x; As[0][ak8 + 5][arow] = pa1.y;
    As[0][ak8 + 6][arow] = pa1.z; As[0][ak8 + 7][arow] = pa1.w;
    *(float4*)&Bs[0][brow][bcol]     = pb0;
    *(float4*)&Bs[0][brow][bcol + 4] = pb1;
    __syncthreads();

    int ntiles = K >> 4;
    for (int t = 0; t < ntiles; t++) {
        int cur = t & 1;
        if (t + 1 < ntiles) {
            const float* ap = aptr + (t + 1) * 16;
            const float* bp = bptr + (size_t)(t + 1) * 16 * ldb;
            pa0 = *(const float4*)(ap);
            pa1 = *(const float4*)(ap + 4);
            pb0 = *(const float4*)(bp);
            pb1 = *(const float4*)(bp + 4);
        }
#pragma unroll
        for (int k = 0; k < 16; k++) {
            F4 af0, af1, bf0, bf1;
            af0.f = *(const float4*)&As[cur][k][ty8];
            af1.f = *(const float4*)&As[cur][k][ty8 + 4];
            bf0.f = *(const float4*)&Bs[cur][k][tx8];
            bf1.f = *(const float4*)&Bs[cur][k][tx8 + 4];
            unsigned long long apair[4] = {af0.u[0], af0.u[1], af1.u[0], af1.u[1]};
            unsigned long long bd[8] = {dup2(bf0.f.x), dup2(bf0.f.y), dup2(bf0.f.z), dup2(bf0.f.w),
                                        dup2(bf1.f.x), dup2(bf1.f.y), dup2(bf1.f.z), dup2(bf1.f.w)};
#pragma unroll
            for (int i = 0; i < 4; i++)
#pragma unroll
                for (int j = 0; j < 8; j++)
                    acc[i][j] = ffma2(apair[i], bd[j], acc[i][j]);
        }
        if (t + 1 < ntiles) {
            int nxt = cur ^ 1;
            As[nxt][ak8 + 0][arow] = pa0.x; As[nxt][ak8 + 1][arow] = pa0.y;
            As[nxt][ak8 + 2][arow] = pa0.z; As[nxt][ak8 + 3][arow] = pa0.w;
            As[nxt][ak8 + 4][arow] = pa1.x; As[nxt][ak8 + 5][arow] = pa1.y;
            As[nxt][ak8 + 6][arow] = pa1.z; As[nxt][ak8 + 7][arow] = pa1.w;
            *(float4*)&Bs[nxt][brow][bcol]     = pb0;
            *(float4*)&Bs[nxt][brow][bcol + 4] = pb1;
            __syncthreads();
        }
    }

    int ncol = bn + tx8;
#pragma unroll
    for (int i = 0; i < 4; i++) {
        float lo[8], hi[8];
#pragma unroll
        for (int j = 0; j < 8; j++) {
            float2 p = unpack2(acc[i][j]);
            lo[j] = p.x; hi[j] = p.y;
        }
        emit_row<EPI>(bm + ty8 + 2 * i,     ncol, lo, M, aux, sidx, scl, Cout, ldc);
        emit_row<EPI>(bm + ty8 + 2 * i + 1, ncol, hi, M, aux, sidx, scl, Cout, ldc);
    }
}

// ---------------- block reduce ----------------------------------------------
__device__ __forceinline__ float blockReduceSum(float v) {
    __shared__ float sh[8];
#pragma unroll
    for (int o = 16; o > 0; o >>= 1) v += __shfl_down_sync(0xffffffffu, v, o);
    int w = threadIdx.x >> 5, l = threadIdx.x & 31;
    if (l == 0) sh[w] = v;
    __syncthreads();
    if (threadIdx.x < 8) {
        float r = sh[threadIdx.x];
#pragma unroll
        for (int o = 4; o > 0; o >>= 1) r += __shfl_down_sync(0x000000ffu, r, o);
        if (threadIdx.x == 0) sh[0] = r;
    }
    __syncthreads();
    float res = sh[0];
    __syncthreads();
    return res;
}

// ---------------- LN1 -------------------------------------------------------
__global__ void ln_kernel(const float* __restrict__ x, const float* __restrict__ w,
                          const float* __restrict__ b, float* __restrict__ out) {
    int row = blockIdx.x;
    int tid = threadIdx.x;
    float4 v = ((const float4*)(x + (size_t)row * CD))[tid];
    float s = v.x + v.y + v.z + v.w;
    s = blockReduceSum(s);
    float mean = s * (1.0f / CD);
    float dx = v.x - mean, dy = v.y - mean, dz = v.z - mean, dw = v.w - mean;
    float s2 = dx * dx + dy * dy + dz * dz + dw * dw;
    s2 = blockReduceSum(s2);
    float rstd = 1.0f / sqrtf(s2 * (1.0f / CD) + 1e-5f);
    float4 wv = ((const float4*)w)[tid];
    float4 bv = ((const float4*)b)[tid];
    float4 o = make_float4(dx * rstd * wv.x + bv.x, dy * rstd * wv.y + bv.y,
                           dz * rstd * wv.z + bv.z, dw * rstd * wv.w + bv.w);
    ((float4*)(out + (size_t)row * CD))[tid] = o;
}

// ---------------- LN2 + routing (conf/diff/affinity/bids/argmax/lists) -------
__global__ void ln2_route_kernel(const float* __restrict__ x2, const float* __restrict__ w,
                                 const float* __restrict__ b,
                                 const float* __restrict__ conf_rwkv,
                                 const float* __restrict__ conf_trans,
                                 const float* __restrict__ w_diff,
                                 const float* __restrict__ W_aff,
                                 const float* __restrict__ capital,
                                 float* __restrict__ h_out, float* __restrict__ scale_out,
                                 int* __restrict__ cnt, int* __restrict__ lst) {
    int row = blockIdx.x;
    int tid = threadIdx.x;
    float4 v = ((const float4*)(x2 + (size_t)row * CD))[tid];
    float s = v.x + v.y + v.z + v.w;
    s = blockReduceSum(s);
    float mean = s * (1.0f / CD);
    float dx = v.x - mean, dy = v.y - mean, dz = v.z - mean, dw = v.w - mean;
    float s2 = dx * dx + dy * dy + dz * dz + dw * dw;
    s2 = blockReduceSum(s2);
    float rstd = 1.0f / sqrtf(s2 * (1.0f / CD) + 1e-5f);
    float4 wv = ((const float4*)w)[tid];
    float4 bv = ((const float4*)b)[tid];
    float4 o = make_float4(dx * rstd * wv.x + bv.x, dy * rstd * wv.y + bv.y,
                           dz * rstd * wv.z + bv.z, dw * rstd * wv.w + bv.w);
    ((float4*)(h_out + (size_t)row * CD))[tid] = o;

    float p[7];
    float4 c0 = ((const float4*)conf_rwkv)[tid];
    float4 c1 = ((const float4*)(conf_rwkv + CD))[tid];
    float4 ct = ((const float4*)conf_trans)[tid];
    float4 wd = ((const float4*)w_diff)[tid];
    p[0] = o.x * c0.x + o.y * c0.y + o.z * c0.z + o.w * c0.w;
    p[1] = o.x * c1.x + o.y * c1.y + o.z * c1.z + o.w * c1.w;
    p[2] = o.x * ct.x + o.y * ct.y + o.z * ct.z + o.w * ct.w;
    p[3] = o.x * wd.x + o.y * wd.y + o.z * wd.z + o.w * wd.w;
    const float* wa = W_aff + (size_t)tid * 4 * 3;   // (C,3) row-major
#pragma unroll
    for (int e = 0; e < 3; e++)
        p[4 + e] = o.x * wa[0 + e] + o.y * wa[3 + e] + o.z * wa[6 + e] + o.w * wa[9 + e];

    __shared__ float red[7][8];
    int wid = tid >> 5, lid = tid & 31;
#pragma unroll
    for (int q = 0; q < 7; q++) {
        float vv = p[q];
#pragma unroll
        for (int o2 = 16; o2 > 0; o2 >>= 1) vv += __shfl_down_sync(0xffffffffu, vv, o2);
        if (lid == 0) red[q][wid] = vv;
    }
    __syncthreads();
    if (tid == 0) {
        float d[7];
#pragma unroll
        for (int q = 0; q < 7; q++) {
            float t = 0.f;
#pragma unroll
            for (int k = 0; k < 8; k++) t += red[q][k];
            d[q] = t;
        }
        float cf[3] = {sigf(d[0]), sigf(d[1]), sigf(d[2])};
        float diff = sigf(d[3]);
        float bids[3];
#pragma unroll
        for (int e = 0; e < 3; e++) bids[e] = cf[e] * capital[e] * diff + d[4 + e];
        int wdx = 0;
        float best = bids[0];
        if (bids[1] > best) { best = bids[1]; wdx = 1; }
        if (bids[2] > best) { best = bids[2]; wdx = 2; }
        float wc = cf[wdx];
        scale_out[row] = wc / (wc + 1e-6f);
        int pos = atomicAdd(&cnt[wdx], 1);
        lst[wdx * NT + pos] = row;
    }
}

__global__ void zero_cnt_kernel(int* c) {
    if (threadIdx.x < 3) c[threadIdx.x] = 0;
}

// ---------------- launch ------------------------------------------------------
extern "C" void kernel_launch(void* const* d_in, const int* in_sizes, int n_in,
                              void* d_out, int out_size) {
    const float* x       = (const float*)d_in[0];
    const float* capital = (const float*)d_in[2];
    const float* ln1w = (const float*)d_in[3], *ln1b = (const float*)d_in[4];
    const float* ln2w = (const float*)d_in[5], *ln2b = (const float*)d_in[6];
    const float* Wr = (const float*)d_in[7], *Wv = (const float*)d_in[8];
    const float* Wo = (const float*)d_in[9], *Ws = (const float*)d_in[10];
    const float* Kr = (const float*)d_in[11], *Vr = (const float*)d_in[12];
    const float* confr = (const float*)d_in[13];
    const float* W1 = (const float*)d_in[14], *W2 = (const float*)d_in[15];
    const float* W3 = (const float*)d_in[16];
    const float* conft = (const float*)d_in[17], *wdiff = (const float*)d_in[18];
    const float* Waff = (const float*)d_in[19];
    float* out = (float*)d_out;

    void* p;
    cudaGetSymbolAddress(&p, g_xln);   float* xln   = (float*)p;
    cudaGetSymbolAddress(&p, g_r);     float* rb    = (float*)p;
    cudaGetSymbolAddress(&p, g_g);     float* gb    = (float*)p;
    cudaGetSymbolAddress(&p, g_s);     float* sb    = (float*)p;
    cudaGetSymbolAddress(&p, g_h);     float* hb    = (float*)p;
    cudaGetSymbolAddress(&p, g_a);     float* ab    = (float*)p;
    cudaGetSymbolAddress(&p, g_hr);    float* hrb   = (float*)p;
    cudaGetSymbolAddress(&p, g_scale); float* sclp  = (float*)p;
    cudaGetSymbolAddress(&p, g_cnt);   int*   cnt   = (int*)p;
    cudaGetSymbolAddress(&p, g_list);  int*   lst   = (int*)p;

    dim3 blk(256);
    dim3 gC(NT / 128, CD / 128);   // (64, 8)
    dim3 gH(NT / 128, HD / 128);   // (64, 32)

    zero_cnt_kernel<<<1, 32>>>(cnt);
    ln_kernel<<<NT, 256>>>(x, ln1w, ln1b, xln);

    // attention path (fp32-exact: feeds routing)
    gemm_k<EPI_STORE><<<gC, blk>>>(xln, Wr, NT, nullptr, CD, CD, nullptr, nullptr, nullptr, nullptr, rb, CD);
    gemm_k<EPI_SIGMUL><<<gC, blk>>>(xln, Wv, NT, nullptr, CD, CD, nullptr, rb, nullptr, nullptr, gb, CD);
    gemm_k<EPI_STORE><<<gC, blk>>>(xln, Ws, NT, nullptr, CD, CD, nullptr, nullptr, nullptr, nullptr, sb, CD);
    gemm_k<EPI_ADDX><<<gC, blk>>>(gb, Wo, NT, nullptr, CD, CD, nullptr, x, nullptr, nullptr, out, CD);

    // LN2 + routing: h, scale, per-expert token lists
    ln2_route_kernel<<<NT, 256>>>(out, ln2w, ln2b, confr, conft, wdiff, Waff,
                                  capital, hb, sclp, cnt, lst);

    // transformer expert (winner == 2), sparse
    gemm_k<EPI_STORE><<<gC, blk>>>(hb, W1, 0, cnt + 2, CD, CD, lst + 2 * NT, nullptr, nullptr, nullptr, ab, CD);
    gemm_k<EPI_GATE><<<gC, blk>>>(sb, W2, 0, cnt + 2, CD, CD, lst + 2 * NT, ab, nullptr, nullptr, ab, CD);
    gemm_k<EPI_SCATTER><<<gC, blk>>>(ab, W3, 0, cnt + 2, CD, CD, nullptr, nullptr, lst + 2 * NT, sclp, out, CD);

    // RWKV experts (winner == e), sparse
    for (int e = 0; e < 2; e++) {
        gemm_k<EPI_RELUSQ><<<gH, blk>>>(hb, Kr + (size_t)e * CD * HD, 0, cnt + e, CD, HD,
                                        lst + e * NT, nullptr, nullptr, nullptr, hrb, HD);
        gemm_k<EPI_SCATTER><<<gC, blk>>>(hrb, Vr + (size_t)e * HD * CD, 0, cnt + e, HD, CD,
                                         nullptr, nullptr, lst + e * NT, sclp, out, CD);
    }
}

// round 3
// speedup vs baseline: 2.8882x; 1.0004x over previous
#include <cuda_runtime.h>
#include <math.h>

#define NT 8192
#define CD 1024
#define HD 4096

// ---------------- scratch (static device globals; no runtime allocation) ----
__device__ __align__(16) float g_xln[NT * CD];
__device__ __align__(16) float g_r[NT * CD];
__device__ __align__(16) float g_g[NT * CD];
__device__ __align__(16) float g_s[NT * CD];
__device__ __align__(16) float g_h[NT * CD];
__device__ __align__(16) float g_a[NT * CD];
__device__ __align__(16) float g_hr[NT * HD];
__device__ float g_scale[NT];
__device__ int g_cnt[3];
__device__ int g_list[3 * NT];

// ---------------- helpers ---------------------------------------------------
__device__ __forceinline__ unsigned long long ffma2(unsigned long long a,
                                                    unsigned long long b,
                                                    unsigned long long c) {
    unsigned long long d;
    asm("fma.rn.f32x2 %0, %1, %2, %3;" : "=l"(d) : "l"(a), "l"(b), "l"(c));
    return d;
}
__device__ __forceinline__ unsigned long long dup2(float v) {
    unsigned long long d;
    unsigned int u = __float_as_uint(v);
    asm("mov.b64 %0, {%1, %2};" : "=l"(d) : "r"(u), "r"(u));
    return d;
}
__device__ __forceinline__ float2 unpack2(unsigned long long v) {
    float2 r;
    asm("mov.b64 {%0, %1}, %2;" : "=f"(r.x), "=f"(r.y) : "l"(v));
    return r;
}
__device__ __forceinline__ float sigf(float x) { return 1.0f / (1.0f + expf(-x)); }

union F4 { float4 f; unsigned long long u[2]; };

enum { EPI_STORE = 0, EPI_ADDX = 1, EPI_SIGMUL = 2, EPI_RELUSQ = 3, EPI_GATE = 4, EPI_SCATTER = 5 };

template <int EPI>
__device__ __forceinline__ void emit_row(int row, int col, const float v[8], int M,
                                         const float* __restrict__ aux,
                                         const int* __restrict__ sidx,
                                         const float* __restrict__ scl,
                                         float* __restrict__ C, int ldc) {
    if (row >= M) return;
    if (EPI == EPI_SCATTER) {
        int orow = sidx[row];
        float sc = scl[orow];
        float* p = C + (size_t)orow * ldc + col;
#pragma unroll
        for (int q = 0; q < 8; q += 4) {
            float4 c = *(float4*)(p + q);
            c.x += v[q + 0] * sc; c.y += v[q + 1] * sc;
            c.z += v[q + 2] * sc; c.w += v[q + 3] * sc;
            *(float4*)(p + q) = c;
        }
        return;
    }
    float* p = C + (size_t)row * ldc + col;
    const float* ap = (EPI == EPI_ADDX || EPI == EPI_SIGMUL || EPI == EPI_GATE)
                          ? aux + (size_t)row * ldc + col : nullptr;
#pragma unroll
    for (int q = 0; q < 8; q += 4) {
        float t0 = v[q + 0], t1 = v[q + 1], t2 = v[q + 2], t3 = v[q + 3];
        if (EPI == EPI_ADDX) {
            float4 a = *(const float4*)(ap + q);
            t0 += a.x; t1 += a.y; t2 += a.z; t3 += a.w;
        }
        if (EPI == EPI_SIGMUL) {
            float4 a = *(const float4*)(ap + q);
            t0 = sigf(a.x) * t0; t1 = sigf(a.y) * t1;
            t2 = sigf(a.z) * t2; t3 = sigf(a.w) * t3;
        }
        if (EPI == EPI_RELUSQ) {
            t0 = fmaxf(t0, 0.f); t0 *= t0;
            t1 = fmaxf(t1, 0.f); t1 *= t1;
            t2 = fmaxf(t2, 0.f); t2 *= t2;
            t3 = fmaxf(t3, 0.f); t3 *= t3;
        }
        if (EPI == EPI_GATE) {
            float4 a = *(const float4*)(ap + q);
            t0 = a.x * sigf(t0); t1 = a.y * sigf(t1);
            t2 = a.z * sigf(t2); t3 = a.w * sigf(t3);
        }
        *(float4*)(p + q) = make_float4(t0, t1, t2, t3);
    }
}

// ------------- 128x128 fp32 GEMM, BK=16, double-buffered, dedup-B f32x2 ------
// C[M,N] (+epilogue) = A[M,K] @ B[K,N].  A rows optionally gathered via gidx.
// M can be dynamic (read from Mptr) for expert dispatch; surplus blocks exit.
template <int EPI>
__global__ void __launch_bounds__(256, 2)
gemm_k(const float* __restrict__ A, const float* __restrict__ B,
       int Mstat, const int* __restrict__ Mptr, int K, int ldb,
       const int* __restrict__ gidx,
       const float* __restrict__ aux,
       const int* __restrict__ sidx, const float* __restrict__ scl,
       float* __restrict__ Cout, int ldc) {
    int M = Mptr ? *Mptr : Mstat;
    int bm = blockIdx.x * 128;
    if (bm >= M) return;
    int bn = blockIdx.y * 128;

    __shared__ __align__(16) float As[2][16][132];  // k-major (transposed A)
    __shared__ __align__(16) float Bs[2][16][128];

    int tid = threadIdx.x;
    // global->smem mappings
    int arow = tid >> 1;            // 0..127
    int ak8  = (tid & 1) * 8;       // 0 / 8
    int brow = tid >> 4;            // 0..15
    int bcol = (tid & 15) * 8;      // 0..120

    int rl = bm + arow;
    int rA = (rl < M) ? rl : (M - 1);
    if (gidx) rA = gidx[rA];
    const float* aptr = A + (size_t)rA * K + ak8;
    const float* bptr = B + (size_t)brow * ldb + bn + bcol;

    int tx = tid & 15, ty = tid >> 4;
    int ty8 = ty * 8, tx8 = tx * 8;

    unsigned long long acc[4][8];
#pragma unroll
    for (int i = 0; i < 4; i++)
#pragma unroll
        for (int j = 0; j < 8; j++) acc[i][j] = 0ull;

    // prologue: load tile 0 into regs, stage to smem buf 0
    float4 pa0 = *(const float4*)(aptr);
    float4 pa1 = *(const float4*)(aptr + 4);
    float4 pb0 = *(const float4*)(bptr);
    float4 pb1 = *(const float4*)(bptr + 4);
    As[0][ak8 + 0][arow] = pa0.x; As[0][ak8 + 1][arow] = pa0.y;
    As[0][ak8 + 2][arow] = pa0.z; As[0][ak8 + 3][arow] = pa0.w;
    As[0][ak8 + 4][arow] = pa1.x; As[0][ak8 + 5][arow] = pa1.y;
    As[0][ak8 + 6][arow] = pa1.z; As[0][ak8 + 7][arow] = pa1.w;
    *(float4*)&Bs[0][brow][bcol]     = pb0;
    *(float4*)&Bs[0][brow][bcol + 4] = pb1;
    __syncthreads();

    int ntiles = K >> 4;
    for (int t = 0; t < ntiles; t++) {
        int cur = t & 1;
        if (t + 1 < ntiles) {
            const float* ap = aptr + (t + 1) * 16;
            const float* bp = bptr + (size_t)(t + 1) * 16 * ldb;
            pa0 = *(const float4*)(ap);
            pa1 = *(const float4*)(ap + 4);
            pb0 = *(const float4*)(bp);
            pb1 = *(const float4*)(bp + 4);
        }
#pragma unroll
        for (int k = 0; k < 16; k++) {
            F4 af0, af1, bf0, bf1;
            af0.f = *(const float4*)&As[cur][k][ty8];
            af1.f = *(const float4*)&As[cur][k][ty8 + 4];
            bf0.f = *(const float4*)&Bs[cur][k][tx8];
            bf1.f = *(const float4*)&Bs[cur][k][tx8 + 4];
            unsigned long long apair[4] = {af0.u[0], af0.u[1], af1.u[0], af1.u[1]};
            unsigned long long bd[8] = {dup2(bf0.f.x), dup2(bf0.f.y), dup2(bf0.f.z), dup2(bf0.f.w),
                                        dup2(bf1.f.x), dup2(bf1.f.y), dup2(bf1.f.z), dup2(bf1.f.w)};
#pragma unroll
            for (int i = 0; i < 4; i++)
#pragma unroll
                for (int j = 0; j < 8; j++)
                    acc[i][j] = ffma2(apair[i], bd[j], acc[i][j]);
        }
        if (t + 1 < ntiles) {
            int nxt = cur ^ 1;
            As[nxt][ak8 + 0][arow] = pa0.x; As[nxt][ak8 + 1][arow] = pa0.y;
            As[nxt][ak8 + 2][arow] = pa0.z; As[nxt][ak8 + 3][arow] = pa0.w;
            As[nxt][ak8 + 4][arow] = pa1.x; As[nxt][ak8 + 5][arow] = pa1.y;
            As[nxt][ak8 + 6][arow] = pa1.z; As[nxt][ak8 + 7][arow] = pa1.w;
            *(float4*)&Bs[nxt][brow][bcol]     = pb0;
            *(float4*)&Bs[nxt][brow][bcol + 4] = pb1;
            __syncthreads();
        }
    }

    int ncol = bn + tx8;
#pragma unroll
    for (int i = 0; i < 4; i++) {
        float lo[8], hi[8];
#pragma unroll
        for (int j = 0; j < 8; j++) {
            float2 p = unpack2(acc[i][j]);
            lo[j] = p.x; hi[j] = p.y;
        }
        emit_row<EPI>(bm + ty8 + 2 * i,     ncol, lo, M, aux, sidx, scl, Cout, ldc);
        emit_row<EPI>(bm + ty8 + 2 * i + 1, ncol, hi, M, aux, sidx, scl, Cout, ldc);
    }
}

// ---------------- block reduce ----------------------------------------------
__device__ __forceinline__ float blockReduceSum(float v) {
    __shared__ float sh[8];
#pragma unroll
    for (int o = 16; o > 0; o >>= 1) v += __shfl_down_sync(0xffffffffu, v, o);
    int w = threadIdx.x >> 5, l = threadIdx.x & 31;
    if (l == 0) sh[w] = v;
    __syncthreads();
    if (threadIdx.x < 8) {
        float r = sh[threadIdx.x];
#pragma unroll
        for (int o = 4; o > 0; o >>= 1) r += __shfl_down_sync(0x000000ffu, r, o);
        if (threadIdx.x == 0) sh[0] = r;
    }
    __syncthreads();
    float res = sh[0];
    __syncthreads();
    return res;
}

// ---------------- LN1 -------------------------------------------------------
__global__ void ln_kernel(const float* __restrict__ x, const float* __restrict__ w,
                          const float* __restrict__ b, float* __restrict__ out) {
    int row = blockIdx.x;
    int tid = threadIdx.x;
    float4 v = ((const float4*)(x + (size_t)row * CD))[tid];
    float s = v.x + v.y + v.z + v.w;
    s = blockReduceSum(s);
    float mean = s * (1.0f / CD);
    float dx = v.x - mean, dy = v.y - mean, dz = v.z - mean, dw = v.w - mean;
    float s2 = dx * dx + dy * dy + dz * dz + dw * dw;
    s2 = blockReduceSum(s2);
    float rstd = 1.0f / sqrtf(s2 * (1.0f / CD) + 1e-5f);
    float4 wv = ((const float4*)w)[tid];
    float4 bv = ((const float4*)b)[tid];
    float4 o = make_float4(dx * rstd * wv.x + bv.x, dy * rstd * wv.y + bv.y,
                           dz * rstd * wv.z + bv.z, dw * rstd * wv.w + bv.w);
    ((float4*)(out + (size_t)row * CD))[tid] = o;
}

// ---------------- LN2 + routing (conf/diff/affinity/bids/argmax/lists) -------
__global__ void ln2_route_kernel(const float* __restrict__ x2, const float* __restrict__ w,
                                 const float* __restrict__ b,
                                 const float* __restrict__ conf_rwkv,
                                 const float* __restrict__ conf_trans,
                                 const float* __restrict__ w_diff,
                                 const float* __restrict__ W_aff,
                                 const float* __restrict__ capital,
                                 float* __restrict__ h_out, float* __restrict__ scale_out,
                                 int* __restrict__ cnt, int* __restrict__ lst) {
    int row = blockIdx.x;
    int tid = threadIdx.x;
    float4 v = ((const float4*)(x2 + (size_t)row * CD))[tid];
    float s = v.x + v.y + v.z + v.w;
    s = blockReduceSum(s);
    float mean = s * (1.0f / CD);
    float dx = v.x - mean, dy = v.y - mean, dz = v.z - mean, dw = v.w - mean;
    float s2 = dx * dx + dy * dy + dz * dz + dw * dw;
    s2 = blockReduceSum(s2);
    float rstd = 1.0f / sqrtf(s2 * (1.0f / CD) + 1e-5f);
    float4 wv = ((const float4*)w)[tid];
    float4 bv = ((const float4*)b)[tid];
    float4 o = make_float4(dx * rstd * wv.x + bv.x, dy * rstd * wv.y + bv.y,
                           dz * rstd * wv.z + bv.z, dw * rstd * wv.w + bv.w);
    ((float4*)(h_out + (size_t)row * CD))[tid] = o;

    float p[7];
    float4 c0 = ((const float4*)conf_rwkv)[tid];
    float4 c1 = ((const float4*)(conf_rwkv + CD))[tid];
    float4 ct = ((const float4*)conf_trans)[tid];
    float4 wd = ((const float4*)w_diff)[tid];
    p[0] = o.x * c0.x + o.y * c0.y + o.z * c0.z + o.w * c0.w;
    p[1] = o.x * c1.x + o.y * c1.y + o.z * c1.z + o.w * c1.w;
    p[2] = o.x * ct.x + o.y * ct.y + o.z * ct.z + o.w * ct.w;
    p[3] = o.x * wd.x + o.y * wd.y + o.z * wd.z + o.w * wd.w;
    const float* wa = W_aff + (size_t)tid * 4 * 3;   // (C,3) row-major
#pragma unroll
    for (int e = 0; e < 3; e++)
        p[4 + e] = o.x * wa[0 + e] + o.y * wa[3 + e] + o.z * wa[6 + e] + o.w * wa[9 + e];

    __shared__ float red[7][8];
    int wid = tid >> 5, lid = tid & 31;
#pragma unroll
    for (int q = 0; q < 7; q++) {
        float vv = p[q];
#pragma unroll
        for (int o2 = 16; o2 > 0; o2 >>= 1) vv += __shfl_down_sync(0xffffffffu, vv, o2);
        if (lid == 0) red[q][wid] = vv;
    }
    __syncthreads();
    if (tid == 0) {
        float d[7];
#pragma unroll
        for (int q = 0; q < 7; q++) {
            float t = 0.f;
#pragma unroll
            for (int k = 0; k < 8; k++) t += red[q][k];
            d[q] = t;
        }
        float cf[3] = {sigf(d[0]), sigf(d[1]), sigf(d[2])};
        float diff = sigf(d[3]);
        float bids[3];
#pragma unroll
        for (int e = 0; e < 3; e++) bids[e] = cf[e] * capital[e] * diff + d[4 + e];
        int wdx = 0;
        float best = bids[0];
        if (bids[1] > best) { best = bids[1]; wdx = 1; }
        if (bids[2] > best) { best = bids[2]; wdx = 2; }
        float wc = cf[wdx];
        scale_out[row] = wc / (wc + 1e-6f);
        int pos = atomicAdd(&cnt[wdx], 1);
        lst[wdx * NT + pos] = row;
    }
}

__global__ void zero_cnt_kernel(int* c) {
    if (threadIdx.x < 3) c[threadIdx.x] = 0;
}

// ---------------- launch ------------------------------------------------------
extern "C" void kernel_launch(void* const* d_in, const int* in_sizes, int n_in,
                              void* d_out, int out_size) {
    const float* x       = (const float*)d_in[0];
    const float* capital = (const float*)d_in[2];
    const float* ln1w = (const float*)d_in[3], *ln1b = (const float*)d_in[4];
    const float* ln2w = (const float*)d_in[5], *ln2b = (const float*)d_in[6];
    const float* Wr = (const float*)d_in[7], *Wv = (const float*)d_in[8];
    const float* Wo = (const float*)d_in[9], *Ws = (const float*)d_in[10];
    const float* Kr = (const float*)d_in[11], *Vr = (const float*)d_in[12];
    const float* confr = (const float*)d_in[13];
    const float* W1 = (const float*)d_in[14], *W2 = (const float*)d_in[15];
    const float* W3 = (const float*)d_in[16];
    const float* conft = (const float*)d_in[17], *wdiff = (const float*)d_in[18];
    const float* Waff = (const float*)d_in[19];
    float* out = (float*)d_out;

    void* p;
    cudaGetSymbolAddress(&p, g_xln);   float* xln   = (float*)p;
    cudaGetSymbolAddress(&p, g_r);     float* rb    = (float*)p;
    cudaGetSymbolAddress(&p, g_g);     float* gb    = (float*)p;
    cudaGetSymbolAddress(&p, g_s);     float* sb    = (float*)p;
    cudaGetSymbolAddress(&p, g_h);     float* hb    = (float*)p;
    cudaGetSymbolAddress(&p, g_a);     float* ab    = (float*)p;
    cudaGetSymbolAddress(&p, g_hr);    float* hrb   = (float*)p;
    cudaGetSymbolAddress(&p, g_scale); float* sclp  = (float*)p;
    cudaGetSymbolAddress(&p, g_cnt);   int*   cnt   = (int*)p;
    cudaGetSymbolAddress(&p, g_list);  int*   lst   = (int*)p;

    dim3 blk(256);
    dim3 gC(NT / 128, CD / 128);   // (64, 8)
    dim3 gH(NT / 128, HD / 128);   // (64, 32)

    zero_cnt_kernel<<<1, 32>>>(cnt);
    ln_kernel<<<NT, 256>>>(x, ln1w, ln1b, xln);

    // attention path (fp32-exact: feeds routing)
    gemm_k<EPI_STORE><<<gC, blk>>>(xln, Wr, NT, nullptr, CD, CD, nullptr, nullptr, nullptr, nullptr, rb, CD);
    gemm_k<EPI_SIGMUL><<<gC, blk>>>(xln, Wv, NT, nullptr, CD, CD, nullptr, rb, nullptr, nullptr, gb, CD);
    gemm_k<EPI_STORE><<<gC, blk>>>(xln, Ws, NT, nullptr, CD, CD, nullptr, nullptr, nullptr, nullptr, sb, CD);
    gemm_k<EPI_ADDX><<<gC, blk>>>(gb, Wo, NT, nullptr, CD, CD, nullptr, x, nullptr, nullptr, out, CD);

    // LN2 + routing: h, scale, per-expert token lists
    ln2_route_kernel<<<NT, 256>>>(out, ln2w, ln2b, confr, conft, wdiff, Waff,
                                  capital, hb, sclp, cnt, lst);

    // transformer expert (winner == 2), sparse
    gemm_k<EPI_STORE><<<gC, blk>>>(hb, W1, 0, cnt + 2, CD, CD, lst + 2 * NT, nullptr, nullptr, nullptr, ab, CD);
    gemm_k<EPI_GATE><<<gC, blk>>>(sb, W2, 0, cnt + 2, CD, CD, lst + 2 * NT, ab, nullptr, nullptr, ab, CD);
    gemm_k<EPI_SCATTER><<<gC, blk>>>(ab, W3, 0, cnt + 2, CD, CD, nullptr, nullptr, lst + 2 * NT, sclp, out, CD);

    // RWKV experts (winner == e), sparse
    for (int e = 0; e < 2; e++) {
        gemm_k<EPI_RELUSQ><<<gH, blk>>>(hb, Kr + (size_t)e * CD * HD, 0, cnt + e, CD, HD,
                                        lst + e * NT, nullptr, nullptr, nullptr, hrb, HD);
        gemm_k<EPI_SCATTER><<<gC, blk>>>(hrb, Vr + (size_t)e * HD * CD, 0, cnt + e, HD, CD,
                                         nullptr, nullptr, lst + e * NT, sclp, out, CD);
    }
}

// round 5
// speedup vs baseline: 4.5522x; 1.5762x over previous
#include <cuda_runtime.h>
#include <cuda_bf16.h>
#include <math.h>
#include <stdint.h>

#define NT 8192
#define CD 1024
#define HD 4096

// ---------------- scratch ----------------------------------------------------
__device__ __align__(16) float g_xln[NT * CD];
__device__ __align__(16) float g_r[NT * CD];
__device__ __align__(16) float g_g[NT * CD];
__device__ __align__(16) float g_s[NT * CD];
__device__ __align__(16) float g_h[NT * CD];
__device__ __align__(16) float g_a[NT * CD];
__device__ float g_scale[NT];
__device__ int g_cnt[3];
__device__ int g_list[3 * NT];
__device__ __align__(16) __nv_bfloat16 g_hhi[NT * CD];
__device__ __align__(16) __nv_bfloat16 g_hlo[NT * CD];
__device__ __align__(16) __nv_bfloat16 g_shi[NT * CD];
__device__ __align__(16) __nv_bfloat16 g_slo[NT * CD];
__device__ __align__(16) __nv_bfloat16 g_ahi[NT * CD];
__device__ __align__(16) __nv_bfloat16 g_alo[NT * CD];
__device__ __align__(16) __nv_bfloat16 g_hrhi[NT * HD];
__device__ __align__(16) __nv_bfloat16 g_hrlo[NT * HD];
#define WSZ (19u * 1048576u)
__device__ __align__(16) __nv_bfloat16 g_wthi[WSZ];
__device__ __align__(16) __nv_bfloat16 g_wtlo[WSZ];

// ---------------- helpers ----------------------------------------------------
__device__ __forceinline__ uint32_t smem_u32(const void* p) {
    uint32_t a;
    asm("{ .reg .u64 t; cvta.to.shared.u64 t, %1; cvt.u32.u64 %0, t; }" : "=r"(a) : "l"(p));
    return a;
}
__device__ __forceinline__ void ldsm4(uint32_t* r, uint32_t a) {
    asm volatile("ldmatrix.sync.aligned.m8n8.x4.shared.b16 {%0,%1,%2,%3}, [%4];"
                 : "=r"(r[0]), "=r"(r[1]), "=r"(r[2]), "=r"(r[3]) : "r"(a));
}
__device__ __forceinline__ void mma16816(float* d, const uint32_t* a, const uint32_t* b) {
    asm volatile("mma.sync.aligned.m16n8k16.row.col.f32.bf16.bf16.f32 "
                 "{%0,%1,%2,%3}, {%4,%5,%6,%7}, {%8,%9}, {%0,%1,%2,%3};"
                 : "+f"(d[0]), "+f"(d[1]), "+f"(d[2]), "+f"(d[3])
                 : "r"(a[0]), "r"(a[1]), "r"(a[2]), "r"(a[3]), "r"(b[0]), "r"(b[1]));
}
__device__ __forceinline__ unsigned long long ffma2(unsigned long long a, unsigned long long b, unsigned long long c) {
    unsigned long long d;
    asm("fma.rn.f32x2 %0, %1, %2, %3;" : "=l"(d) : "l"(a), "l"(b), "l"(c));
    return d;
}
__device__ __forceinline__ unsigned long long dup2(float v) {
    unsigned long long d; unsigned u = __float_as_uint(v);
    asm("mov.b64 %0, {%1, %2};" : "=l"(d) : "r"(u), "r"(u));
    return d;
}
__device__ __forceinline__ float2 unpack2(unsigned long long v) {
    float2 r;
    asm("mov.b64 {%0, %1}, %2;" : "=f"(r.x), "=f"(r.y) : "l"(v));
    return r;
}
__device__ __forceinline__ float sigf(float x) { return 1.0f / (1.0f + expf(-x)); }
__device__ __forceinline__ unsigned packbf(__nv_bfloat16 a, __nv_bfloat16 b) {
    return (unsigned)__bfloat16_as_ushort(a) | ((unsigned)__bfloat16_as_ushort(b) << 16);
}
union F4 { float4 f; unsigned long long u[2]; };

// ================= HMMA tensor GEMM (bf16x3 emulated fp32) ====================
// D[128,128] tile of A[M,K] @ B[N,K]^T.  hi/lo split operands, 3-term accum.
enum { TEPI_HR = 0, TEPI_STORE = 1, TEPI_GATE = 2, TEPI_SCATTER = 3 };
#define TG_SMEM (2 * 32768 + 1024)

template <int EPI>
__device__ __forceinline__ void emit2(int grow, int gcol, float v0, float v1, int M,
                                      const float* __restrict__ aux,
                                      const int* __restrict__ sidx, const float* __restrict__ scl,
                                      float* __restrict__ outF,
                                      __nv_bfloat16* __restrict__ outHi,
                                      __nv_bfloat16* __restrict__ outLo, int ldo) {
    if (grow >= M) return;
    if (EPI == TEPI_STORE) {
        *(float2*)(outF + (size_t)grow * ldo + gcol) = make_float2(v0, v1);
    } else if (EPI == TEPI_SCATTER) {
        int orow = sidx[grow];
        float sc = scl[orow];
        float2* p = (float2*)(outF + (size_t)orow * ldo + gcol);
        float2 c = *p;
        c.x += v0 * sc; c.y += v1 * sc;
        *p = c;
    } else {
        if (EPI == TEPI_HR) {
            v0 = fmaxf(v0, 0.f); v0 *= v0;
            v1 = fmaxf(v1, 0.f); v1 *= v1;
        } else {
            float2 a = *(const float2*)(aux + (size_t)grow * ldo + gcol);
            v0 = a.x * sigf(v0); v1 = a.y * sigf(v1);
        }
        __nv_bfloat16 h0 = __float2bfloat16(v0), h1 = __float2bfloat16(v1);
        *(unsigned*)(outHi + (size_t)grow * ldo + gcol) = packbf(h0, h1);
        *(unsigned*)(outLo + (size_t)grow * ldo + gcol) =
            packbf(__float2bfloat16(v0 - __bfloat162float(h0)),
                   __float2bfloat16(v1 - __bfloat162float(h1)));
    }
}

template <int EPI>
__global__ void __launch_bounds__(256)
tgemm(const __nv_bfloat16* __restrict__ Ahi, const __nv_bfloat16* __restrict__ Alo,
      const __nv_bfloat16* __restrict__ Bhi, const __nv_bfloat16* __restrict__ Blo,
      const int* __restrict__ Mptr, int K,
      const int* __restrict__ gidx, const float* __restrict__ aux,
      const int* __restrict__ sidx, const float* __restrict__ scl,
      float* __restrict__ outF,
      __nv_bfloat16* __restrict__ outHi, __nv_bfloat16* __restrict__ outLo, int ldo) {
    int M = *Mptr;
    int bm = blockIdx.x * 128;
    if (bm >= M) return;
    int bn = blockIdx.y * 128;

    extern __shared__ char smraw[];
    uint32_t smb0 = smem_u32(smraw);
    uint32_t smb = (smb0 + 1023u) & ~1023u;
    char* sb = smraw + (smb - smb0);
    // buffer b (b=0,1): A tile at b*32768, B tile at b*32768+16384
    // row layout (A and B): 128 rows x 128B; hi bytes 0-63 (k*2), lo bytes 64-127
    // swizzle: byte col c -> c ^ ((row&7)<<4)

    int tid = threadIdx.x, lane = tid & 31, warp = tid >> 5;
    int wm = warp & 1, wn = warp >> 1;       // 2x4 warp grid: 64 rows x 32 cols each
    int quad = lane >> 3, r8 = lane & 7;

    // ldmatrix address precompute
    uint32_t baseA[4], maskA[4];
    uint32_t kqA = (uint32_t)(quad >> 1) * 16;   // A: quad>>1 selects k8 (bytes)
#pragma unroll
    for (int mt = 0; mt < 4; mt++) {
        int rowA = wm * 64 + mt * 16 + (quad & 1) * 8 + r8;
        baseA[mt] = (uint32_t)rowA * 128;
        maskA[mt] = (uint32_t)(rowA & 7) << 4;
    }
    uint32_t baseB[2], maskB[2];
    uint32_t kqB = (uint32_t)(quad & 1) * 16;    // B: quad&1 selects k8
#pragma unroll
    for (int n2 = 0; n2 < 2; n2++) {
        int rowB = wn * 32 + n2 * 16 + (quad >> 1) * 8 + r8;
        baseB[n2] = 16384u + (uint32_t)rowB * 128;
        maskB[n2] = (uint32_t)(rowB & 7) << 4;
    }

    // global staging mapping: 2 threads per row; each loads 16 bf16 hi + 16 lo per array
    int row = tid >> 1, h = tid & 1;
    int ra = bm + row; if (ra > M - 1) ra = M - 1;
    if (gidx) ra = gidx[ra];
    const __nv_bfloat16* pAh = Ahi + (size_t)ra * K + h * 16;
    const __nv_bfloat16* pAl = Alo + (size_t)ra * K + h * 16;
    const __nv_bfloat16* pBh = Bhi + (size_t)(bn + row) * K + h * 16;
    const __nv_bfloat16* pBl = Blo + (size_t)(bn + row) * K + h * 16;
    uint32_t mk = (uint32_t)(row & 7) << 4;
    uint32_t st0 = (uint32_t)row * 128 + (((uint32_t)h * 32) ^ mk);
    uint32_t st1 = (uint32_t)row * 128 + (((uint32_t)h * 32 + 16) ^ mk);
    uint32_t st2 = (uint32_t)row * 128 + ((64u + h * 32) ^ mk);
    uint32_t st3 = (uint32_t)row * 128 + ((64u + h * 32 + 16) ^ mk);

    float acc[4][4][4];
#pragma unroll
    for (int i = 0; i < 4; i++)
#pragma unroll
        for (int j = 0; j < 4; j++)
#pragma unroll
            for (int q = 0; q < 4; q++) acc[i][j][q] = 0.f;

    uint4 sah0, sah1, sal0, sal1, sbh0, sbh1, sbl0, sbl1;

    // prologue: chunk 0
    sah0 = *(const uint4*)(pAh); sah1 = *(const uint4*)(pAh + 8);
    sal0 = *(const uint4*)(pAl); sal1 = *(const uint4*)(pAl + 8);
    sbh0 = *(const uint4*)(pBh); sbh1 = *(const uint4*)(pBh + 8);
    sbl0 = *(const uint4*)(pBl); sbl1 = *(const uint4*)(pBl + 8);
    {
        char* bp = sb;
        *(uint4*)(bp + st0) = sah0; *(uint4*)(bp + st1) = sah1;
        *(uint4*)(bp + st2) = sal0; *(uint4*)(bp + st3) = sal1;
        bp += 16384;
        *(uint4*)(bp + st0) = sbh0; *(uint4*)(bp + st1) = sbh1;
        *(uint4*)(bp + st2) = sbl0; *(uint4*)(bp + st3) = sbl1;
    }
    __syncthreads();

    int nch = K >> 5;
    for (int t = 0; t < nch; t++) {
        uint32_t bufs = smb + (uint32_t)(t & 1) * 32768u;
        if (t + 1 < nch) {
            int kc = (t + 1) * 32;
            sah0 = *(const uint4*)(pAh + kc); sah1 = *(const uint4*)(pAh + kc + 8);
            sal0 = *(const uint4*)(pAl + kc); sal1 = *(const uint4*)(pAl + kc + 8);
            sbh0 = *(const uint4*)(pBh + kc); sbh1 = *(const uint4*)(pBh + kc + 8);
            sbl0 = *(const uint4*)(pBl + kc); sbl1 = *(const uint4*)(pBl + kc + 8);
        }
#pragma unroll
        for (int ks = 0; ks < 2; ks++) {
            uint32_t cbase = kqA + (uint32_t)ks * 32;
            uint32_t ah[4][4], al[4][4], bh[4][2], bl[4][2];
#pragma unroll
            for (int mt = 0; mt < 4; mt++) {
                ldsm4(ah[mt], bufs + baseA[mt] + (cbase ^ maskA[mt]));
                ldsm4(al[mt], bufs + baseA[mt] + ((cbase + 64u) ^ maskA[mt]));
            }
            uint32_t cbB = kqB + (uint32_t)ks * 32;
#pragma unroll
            for (int n2 = 0; n2 < 2; n2++) {
                uint32_t r[4];
                ldsm4(r, bufs + baseB[n2] + (cbB ^ maskB[n2]));
                bh[2 * n2][0] = r[0]; bh[2 * n2][1] = r[1];
                bh[2 * n2 + 1][0] = r[2]; bh[2 * n2 + 1][1] = r[3];
                ldsm4(r, bufs + baseB[n2] + ((cbB + 64u) ^ maskB[n2]));
                bl[2 * n2][0] = r[0]; bl[2 * n2][1] = r[1];
                bl[2 * n2 + 1][0] = r[2]; bl[2 * n2 + 1][1] = r[3];
            }
#pragma unroll
            for (int mt = 0; mt < 4; mt++)
#pragma unroll
                for (int nt = 0; nt < 4; nt++) {
                    mma16816(acc[mt][nt], ah[mt], bh[nt]);
                    mma16816(acc[mt][nt], ah[mt], bl[nt]);
                    mma16816(acc[mt][nt], al[mt], bh[nt]);
                }
        }
        if (t + 1 < nch) {
            char* bp = sb + ((t + 1) & 1) * 32768;
            *(uint4*)(bp + st0) = sah0; *(uint4*)(bp + st1) = sah1;
            *(uint4*)(bp + st2) = sal0; *(uint4*)(bp + st3) = sal1;
            bp += 16384;
            *(uint4*)(bp + st0) = sbh0; *(uint4*)(bp + st1) = sbh1;
            *(uint4*)(bp + st2) = sbl0; *(uint4*)(bp + st3) = sbl1;
            __syncthreads();
        }
    }

    // epilogue
    int erow = lane >> 2, ecol = (lane & 3) * 2;
#pragma unroll
    for (int mt = 0; mt < 4; mt++) {
        int gr = bm + wm * 64 + mt * 16 + erow;
#pragma unroll
        for (int nt = 0; nt < 4; nt++) {
            int gc = bn + wn * 32 + nt * 8 + ecol;
            emit2<EPI>(gr,     gc, acc[mt][nt][0], acc[mt][nt][1], M, aux, sidx, scl, outF, outHi, outLo, ldo);
            emit2<EPI>(gr + 8, gc, acc[mt][nt][2], acc[mt][nt][3], M, aux, sidx, scl, outF, outHi, outLo, ldo);
        }
    }
}

// ======== transpose + split: W[K,N] -> WT_hi/lo[N,K] (bf16) ===================
__global__ void tsplit(const float* __restrict__ W, int K, int N,
                       __nv_bfloat16* __restrict__ hi, __nv_bfloat16* __restrict__ lo) {
    __shared__ float t[32][33];
    int n0 = blockIdx.x * 32, k0 = blockIdx.y * 32;
    int tx = threadIdx.x, ty = threadIdx.y;
#pragma unroll
    for (int j = 0; j < 4; j++)
        t[ty + 8 * j][tx] = W[(size_t)(k0 + ty + 8 * j) * N + n0 + tx];
    __syncthreads();
#pragma unroll
    for (int j = 0; j < 4; j++) {
        float v = t[tx][ty + 8 * j];
        size_t o = (size_t)(n0 + ty + 8 * j) * K + k0 + tx;
        __nv_bfloat16 h = __float2bfloat16(v);
        hi[o] = h;
        lo[o] = __float2bfloat16(v - __bfloat162float(h));
    }
}

__global__ void asplit(const float* __restrict__ in, __nv_bfloat16* __restrict__ hi,
                       __nv_bfloat16* __restrict__ lo) {
    size_t i = ((size_t)blockIdx.x * 256 + threadIdx.x) * 4;
    float4 v = *(const float4*)(in + i);
    __nv_bfloat16 h0 = __float2bfloat16(v.x), h1 = __float2bfloat16(v.y);
    __nv_bfloat16 h2 = __float2bfloat16(v.z), h3 = __float2bfloat16(v.w);
    *(uint2*)(hi + i) = make_uint2(packbf(h0, h1), packbf(h2, h3));
    *(uint2*)(lo + i) = make_uint2(
        packbf(__float2bfloat16(v.x - __bfloat162float(h0)), __float2bfloat16(v.y - __bfloat162float(h1))),
        packbf(__float2bfloat16(v.z - __bfloat162float(h2)), __float2bfloat16(v.w - __bfloat162float(h3))));
}

// ================= fp32 f32x2 SGEMM (attention path only) =====================
enum { EPI_STORE = 0, EPI_ADDX = 1, EPI_SIGMUL = 2 };

template <int EPI>
__global__ void __launch_bounds__(256, 2)
gemm_k(const float* __restrict__ A, const float* __restrict__ B, int K, int ldb,
       const float* __restrict__ aux, float* __restrict__ Cout, int ldc) {
    int bm = blockIdx.x * 128, bn = blockIdx.y * 128;
    __shared__ __align__(16) float As[2][16][132];
    __shared__ __align__(16) float Bs[2][16][128];
    int tid = threadIdx.x;
    int arow = tid >> 1, ak8 = (tid & 1) * 8;
    int brow = tid >> 4, bcol = (tid & 15) * 8;
    const float* aptr = A + (size_t)(bm + arow) * K + ak8;
    const float* bptr = B + (size_t)brow * ldb + bn + bcol;
    int tx = tid & 15, ty = tid >> 4, ty8 = ty * 8, tx8 = tx * 8;

    unsigned long long acc[4][8];
#pragma unroll
    for (int i = 0; i < 4; i++)
#pragma unroll
        for (int j = 0; j < 8; j++) acc[i][j] = 0ull;

    float4 pa0 = *(const float4*)(aptr), pa1 = *(const float4*)(aptr + 4);
    float4 pb0 = *(const float4*)(bptr), pb1 = *(const float4*)(bptr + 4);
    As[0][ak8 + 0][arow] = pa0.x; As[0][ak8 + 1][arow] = pa0.y;
    As[0][ak8 + 2][arow] = pa0.z; As[0][ak8 + 3][arow] = pa0.w;
    As[0][ak8 + 4][arow] = pa1.x; As[0][ak8 + 5][arow] = pa1.y;
    As[0][ak8 + 6][arow] = pa1.z; As[0][ak8 + 7][arow] = pa1.w;
    *(float4*)&Bs[0][brow][bcol] = pb0;
    *(float4*)&Bs[0][brow][bcol + 4] = pb1;
    __syncthreads();

    int ntiles = K >> 4;
    for (int t = 0; t < ntiles; t++) {
        int cur = t & 1;
        if (t + 1 < ntiles) {
            const float* ap = aptr + (t + 1) * 16;
            const float* bp = bptr + (size_t)(t + 1) * 16 * ldb;
            pa0 = *(const float4*)(ap); pa1 = *(const float4*)(ap + 4);
            pb0 = *(const float4*)(bp); pb1 = *(const float4*)(bp + 4);
        }
#pragma unroll
        for (int k = 0; k < 16; k++) {
            F4 af0, af1, bf0, bf1;
            af0.f = *(const float4*)&As[cur][k][ty8];
            af1.f = *(const float4*)&As[cur][k][ty8 + 4];
            bf0.f = *(const float4*)&Bs[cur][k][tx8];
            bf1.f = *(const float4*)&Bs[cur][k][tx8 + 4];
            unsigned long long ap2[4] = {af0.u[0], af0.u[1], af1.u[0], af1.u[1]};
            unsigned long long bd[8] = {dup2(bf0.f.x), dup2(bf0.f.y), dup2(bf0.f.z), dup2(bf0.f.w),
                                        dup2(bf1.f.x), dup2(bf1.f.y), dup2(bf1.f.z), dup2(bf1.f.w)};
#pragma unroll
            for (int i = 0; i < 4; i++)
#pragma unroll
                for (int j = 0; j < 8; j++) acc[i][j] = ffma2(ap2[i], bd[j], acc[i][j]);
        }
        if (t + 1 < ntiles) {
            int nxt = cur ^ 1;
            As[nxt][ak8 + 0][arow] = pa0.x; As[nxt][ak8 + 1][arow] = pa0.y;
            As[nxt][ak8 + 2][arow] = pa0.z; As[nxt][ak8 + 3][arow] = pa0.w;
            As[nxt][ak8 + 4][arow] = pa1.x; As[nxt][ak8 + 5][arow] = pa1.y;
            As[nxt][ak8 + 6][arow] = pa1.z; As[nxt][ak8 + 7][arow] = pa1.w;
            *(float4*)&Bs[nxt][brow][bcol] = pb0;
            *(float4*)&Bs[nxt][brow][bcol + 4] = pb1;
            __syncthreads();
        }
    }

    int ncol = bn + tx8;
#pragma unroll
    for (int i = 0; i < 4; i++) {
        float lo[8], hi[8];
#pragma unroll
        for (int j = 0; j < 8; j++) { float2 p = unpack2(acc[i][j]); lo[j] = p.x; hi[j] = p.y; }
#pragma unroll
        for (int half = 0; half < 2; half++) {
            const float* v = half ? hi : lo;
            int rowi = bm + ty8 + 2 * i + half;
            float* p = Cout + (size_t)rowi * ldc + ncol;
            const float* ap = (EPI != EPI_STORE) ? aux + (size_t)rowi * ldc + ncol : nullptr;
#pragma unroll
            for (int q = 0; q < 8; q += 4) {
                float t0 = v[q], t1 = v[q + 1], t2 = v[q + 2], t3 = v[q + 3];
                if (EPI == EPI_ADDX) {
                    float4 a = *(const float4*)(ap + q);
                    t0 += a.x; t1 += a.y; t2 += a.z; t3 += a.w;
                }
                if (EPI == EPI_SIGMUL) {
                    float4 a = *(const float4*)(ap + q);
                    t0 = sigf(a.x) * t0; t1 = sigf(a.y) * t1; t2 = sigf(a.z) * t2; t3 = sigf(a.w) * t3;
                }
                *(float4*)(p + q) = make_float4(t0, t1, t2, t3);
            }
        }
    }
}

// ================= LN / routing ===============================================
__device__ __forceinline__ float blockReduceSum(float v) {
    __shared__ float sh[8];
#pragma unroll
    for (int o = 16; o > 0; o >>= 1) v += __shfl_down_sync(0xffffffffu, v, o);
    int w = threadIdx.x >> 5, l = threadIdx.x & 31;
    if (l == 0) sh[w] = v;
    __syncthreads();
    if (threadIdx.x < 8) {
        float r = sh[threadIdx.x];
#pragma unroll
        for (int o = 4; o > 0; o >>= 1) r += __shfl_down_sync(0x000000ffu, r, o);
        if (threadIdx.x == 0) sh[0] = r;
    }
    __syncthreads();
    float res = sh[0];
    __syncthreads();
    return res;
}

__global__ void ln_kernel(const float* __restrict__ x, const float* __restrict__ w,
                          const float* __restrict__ b, float* __restrict__ out) {
    int row = blockIdx.x, tid = threadIdx.x;
    float4 v = ((const float4*)(x + (size_t)row * CD))[tid];
    float s = blockReduceSum(v.x + v.y + v.z + v.w);
    float mean = s * (1.0f / CD);
    float dx = v.x - mean, dy = v.y - mean, dz = v.z - mean, dw = v.w - mean;
    float s2 = blockReduceSum(dx * dx + dy * dy + dz * dz + dw * dw);
    float rstd = 1.0f / sqrtf(s2 * (1.0f / CD) + 1e-5f);
    float4 wv = ((const float4*)w)[tid], bv = ((const float4*)b)[tid];
    ((float4*)(out + (size_t)row * CD))[tid] =
        make_float4(dx * rstd * wv.x + bv.x, dy * rstd * wv.y + bv.y,
                    dz * rstd * wv.z + bv.z, dw * rstd * wv.w + bv.w);
}

__global__ void ln2_route_kernel(const float* __restrict__ x2, const float* __restrict__ w,
                                 const float* __restrict__ b, const float* __restrict__ conf_rwkv,
                                 const float* __restrict__ conf_trans, const float* __restrict__ w_diff,
                                 const float* __restrict__ W_aff, const float* __restrict__ capital,
                                 float* __restrict__ h_out, float* __restrict__ scale_out,
                                 int* __restrict__ cnt, int* __restrict__ lst) {
    int row = blockIdx.x, tid = threadIdx.x;
    float4 v = ((const float4*)(x2 + (size_t)row * CD))[tid];
    float s = blockReduceSum(v.x + v.y + v.z + v.w);
    float mean = s * (1.0f / CD);
    float dx = v.x - mean, dy = v.y - mean, dz = v.z - mean, dw = v.w - mean;
    float s2 = blockReduceSum(dx * dx + dy * dy + dz * dz + dw * dw);
    float rstd = 1.0f / sqrtf(s2 * (1.0f / CD) + 1e-5f);
    float4 wv = ((const float4*)w)[tid], bv = ((const float4*)b)[tid];
    float4 o = make_float4(dx * rstd * wv.x + bv.x, dy * rstd * wv.y + bv.y,
                           dz * rstd * wv.z + bv.z, dw * rstd * wv.w + bv.w);
    ((float4*)(h_out + (size_t)row * CD))[tid] = o;

    float p[7];
    float4 c0 = ((const float4*)conf_rwkv)[tid];
    float4 c1 = ((const float4*)(conf_rwkv + CD))[tid];
    float4 ct = ((const float4*)conf_trans)[tid];
    float4 wd = ((const float4*)w_diff)[tid];
    p[0] = o.x * c0.x + o.y * c0.y + o.z * c0.z + o.w * c0.w;
    p[1] = o.x * c1.x + o.y * c1.y + o.z * c1.z + o.w * c1.w;
    p[2] = o.x * ct.x + o.y * ct.y + o.z * ct.z + o.w * ct.w;
    p[3] = o.x * wd.x + o.y * wd.y + o.z * wd.z + o.w * wd.w;
    const float* wa = W_aff + (size_t)tid * 12;
#pragma unroll
    for (int e = 0; e < 3; e++)
        p[4 + e] = o.x * wa[e] + o.y * wa[3 + e] + o.z * wa[6 + e] + o.w * wa[9 + e];

    __shared__ float red[7][8];
    int wid = tid >> 5, lid = tid & 31;
#pragma unroll
    for (int q = 0; q < 7; q++) {
        float vv = p[q];
#pragma unroll
        for (int o2 = 16; o2 > 0; o2 >>= 1) vv += __shfl_down_sync(0xffffffffu, vv, o2);
        if (lid == 0) red[q][wid] = vv;
    }
    __syncthreads();
    if (tid == 0) {
        float d[7];
#pragma unroll
        for (int q = 0; q < 7; q++) {
            float t = 0.f;
#pragma unroll
            for (int k = 0; k < 8; k++) t += red[q][k];
            d[q] = t;
        }
        float cf[3] = {sigf(d[0]), sigf(d[1]), sigf(d[2])};
        float diff = sigf(d[3]);
        int wdx = 0; float best = -1e30f;
#pragma unroll
        for (int e = 0; e < 3; e++) {
            float bid = cf[e] * capital[e] * diff + d[4 + e];
            if (bid > best) { best = bid; wdx = e; }
        }
        float wc = cf[wdx];
        scale_out[row] = wc / (wc + 1e-6f);
        int pos = atomicAdd(&cnt[wdx], 1);
        lst[wdx * NT + pos] = row;
    }
}

__global__ void zero_cnt_kernel(int* c) { if (threadIdx.x < 3) c[threadIdx.x] = 0; }

// ================= launch =====================================================
extern "C" void kernel_launch(void* const* d_in, const int* in_sizes, int n_in,
                              void* d_out, int out_size) {
    const float* x = (const float*)d_in[0];
    const float* capital = (const float*)d_in[2];
    const float* ln1w = (const float*)d_in[3], *ln1b = (const float*)d_in[4];
    const float* ln2w = (const float*)d_in[5], *ln2b = (const float*)d_in[6];
    const float* Wr = (const float*)d_in[7], *Wv = (const float*)d_in[8];
    const float* Wo = (const float*)d_in[9], *Ws = (const float*)d_in[10];
    const float* Kr = (const float*)d_in[11], *Vr = (const float*)d_in[12];
    const float* confr = (const float*)d_in[13];
    const float* W1 = (const float*)d_in[14], *W2 = (const float*)d_in[15];
    const float* W3 = (const float*)d_in[16];
    const float* conft = (const float*)d_in[17], *wdiff = (const float*)d_in[18];
    const float* Waff = (const float*)d_in[19];
    float* out = (float*)d_out;

    void* p;
    cudaGetSymbolAddress(&p, g_xln);   float* xln = (float*)p;
    cudaGetSymbolAddress(&p, g_r);     float* rb = (float*)p;
    cudaGetSymbolAddress(&p, g_g);     float* gb = (float*)p;
    cudaGetSymbolAddress(&p, g_s);     float* sb = (float*)p;
    cudaGetSymbolAddress(&p, g_h);     float* hb = (float*)p;
    cudaGetSymbolAddress(&p, g_a);     float* ab = (float*)p;
    cudaGetSymbolAddress(&p, g_scale); float* sclp = (float*)p;
    cudaGetSymbolAddress(&p, g_cnt);   int* cnt = (int*)p;
    cudaGetSymbolAddress(&p, g_list);  int* lst = (int*)p;
    cudaGetSymbolAddress(&p, g_hhi);   __nv_bfloat16* hhi = (__nv_bfloat16*)p;
    cudaGetSymbolAddress(&p, g_hlo);   __nv_bfloat16* hlo = (__nv_bfloat16*)p;
    cudaGetSymbolAddress(&p, g_shi);   __nv_bfloat16* shi = (__nv_bfloat16*)p;
    cudaGetSymbolAddress(&p, g_slo);   __nv_bfloat16* slo = (__nv_bfloat16*)p;
    cudaGetSymbolAddress(&p, g_ahi);   __nv_bfloat16* ahi = (__nv_bfloat16*)p;
    cudaGetSymbolAddress(&p, g_alo);   __nv_bfloat16* alo = (__nv_bfloat16*)p;
    cudaGetSymbolAddress(&p, g_hrhi);  __nv_bfloat16* hrhi = (__nv_bfloat16*)p;
    cudaGetSymbolAddress(&p, g_hrlo);  __nv_bfloat16* hrlo = (__nv_bfloat16*)p;
    cudaGetSymbolAddress(&p, g_wthi);  __nv_bfloat16* wthi = (__nv_bfloat16*)p;
    cudaGetSymbolAddress(&p, g_wtlo);  __nv_bfloat16* wtlo = (__nv_bfloat16*)p;

    cudaFuncSetAttribute(tgemm<TEPI_HR>,      cudaFuncAttributeMaxDynamicSharedMemorySize, TG_SMEM);
    cudaFuncSetAttribute(tgemm<TEPI_STORE>,   cudaFuncAttributeMaxDynamicSharedMemorySize, TG_SMEM);
    cudaFuncSetAttribute(tgemm<TEPI_GATE>,    cudaFuncAttributeMaxDynamicSharedMemorySize, TG_SMEM);
    cudaFuncSetAttribute(tgemm<TEPI_SCATTER>, cudaFuncAttributeMaxDynamicSharedMemorySize, TG_SMEM);

    const size_t M1 = 1048576;
    const size_t KR0T = 0, KR1T = 4 * M1, VR0T = 8 * M1, VR1T = 12 * M1;
    const size_t W1T = 16 * M1, W2T = 17 * M1, W3T = 18 * M1;

    dim3 blk(256), tb(32, 8);
    dim3 gC(NT / 128, CD / 128), gH(NT / 128, HD / 128);

    // weight transpose+split (bf16 hi/lo)
    tsplit<<<dim3(HD / 32, CD / 32), tb>>>(Kr, CD, HD, wthi + KR0T, wtlo + KR0T);
    tsplit<<<dim3(HD / 32, CD / 32), tb>>>(Kr + (size_t)CD * HD, CD, HD, wthi + KR1T, wtlo + KR1T);
    tsplit<<<dim3(CD / 32, HD / 32), tb>>>(Vr, HD, CD, wthi + VR0T, wtlo + VR0T);
    tsplit<<<dim3(CD / 32, HD / 32), tb>>>(Vr + (size_t)HD * CD, HD, CD, wthi + VR1T, wtlo + VR1T);
    tsplit<<<dim3(CD / 32, CD / 32), tb>>>(W1, CD, CD, wthi + W1T, wtlo + W1T);
    tsplit<<<dim3(CD / 32, CD / 32), tb>>>(W2, CD, CD, wthi + W2T, wtlo + W2T);
    tsplit<<<dim3(CD / 32, CD / 32), tb>>>(W3, CD, CD, wthi + W3T, wtlo + W3T);

    zero_cnt_kernel<<<1, 32>>>(cnt);
    ln_kernel<<<NT, 256>>>(x, ln1w, ln1b, xln);

    // attention path (fp32-exact: feeds routing)
    gemm_k<EPI_STORE><<<gC, blk>>>(xln, Wr, CD, CD, nullptr, rb, CD);
    gemm_k<EPI_SIGMUL><<<gC, blk>>>(xln, Wv, CD, CD, rb, gb, CD);
    gemm_k<EPI_STORE><<<gC, blk>>>(xln, Ws, CD, CD, nullptr, sb, CD);
    gemm_k<EPI_ADDX><<<gC, blk>>>(gb, Wo, CD, CD, x, out, CD);

    ln2_route_kernel<<<NT, 256>>>(out, ln2w, ln2b, confr, conft, wdiff, Waff,
                                  capital, hb, sclp, cnt, lst);
    asplit<<<NT * CD / 1024, 256>>>(hb, hhi, hlo);
    asplit<<<NT * CD / 1024, 256>>>(sb, shi, slo);

    // transformer expert (winner == 2): HMMA bf16x3
    tgemm<TEPI_STORE><<<gC, blk, TG_SMEM>>>(hhi, hlo, wthi + W1T, wtlo + W1T, cnt + 2, CD,
                                            lst + 2 * NT, nullptr, nullptr, nullptr, ab, nullptr, nullptr, CD);
    tgemm<TEPI_GATE><<<gC, blk, TG_SMEM>>>(shi, slo, wthi + W2T, wtlo + W2T, cnt + 2, CD,
                                           lst + 2 * NT, ab, nullptr, nullptr, nullptr, ahi, alo, CD);
    tgemm<TEPI_SCATTER><<<gC, blk, TG_SMEM>>>(ahi, alo, wthi + W3T, wtlo + W3T, cnt + 2, CD,
                                              nullptr, nullptr, lst + 2 * NT, sclp, out, nullptr, nullptr, CD);

    // RWKV experts: HMMA bf16x3
    for (int e = 0; e < 2; e++) {
        tgemm<TEPI_HR><<<gH, blk, TG_SMEM>>>(hhi, hlo, wthi + (e ? KR1T : KR0T), wtlo + (e ? KR1T : KR0T),
                                             cnt + e, CD, lst + e * NT, nullptr, nullptr, nullptr,
                                             nullptr, hrhi, hrlo, HD);
        tgemm<TEPI_SCATTER><<<gC, blk, TG_SMEM>>>(hrhi, hrlo, wthi + (e ? VR1T : VR0T), wtlo + (e ? VR1T : VR0T),
                                                  cnt + e, HD, nullptr, nullptr, lst + e * NT, sclp,
                                                  out, nullptr, nullptr, CD);
    }
}